// round 1
// baseline (speedup 1.0000x reference)
#include <cuda_runtime.h>

#define D_ 32
#define H_ 64
#define W_ 128
#define SP_TOTAL (2 * D_ * H_ * W_)   // 524288 spatial points (B=2)

// Scratch: normalized neighbor weights (26 ch), center weight, ping-pong volumes.
__device__ float g_w [26 * SP_TOTAL];  // [oc][b,d,h,w]  (channel-major for coalescing)
__device__ float g_w0[SP_TOTAL];
__device__ float g_b0[SP_TOTAL];
__device__ float g_b1[SP_TOTAL];

// ---------------------------------------------------------------------------
// Fused conv3d (27 output channels) + CSPN normalization.
// Block: (16,8)=128 threads. Tile: d_t=1, h_t=8, w_t=64; each thread owns
// 4 w-points strided by 16 (keeps LDS conflict-free and STG coalesced).
// ---------------------------------------------------------------------------
__global__ __launch_bounds__(128, 2)
void conv_norm_kernel(const float* __restrict__ x,
                      const float* __restrict__ wg,
                      const float* __restrict__ wc)
{
    __shared__ float xs[3 * 10 * 80];   // halo tile: [dz 3][hy 10][wx 66] stride 80
    __shared__ float ws[729];           // weights for current input channel: [tap][oc]

    const int tx  = threadIdx.x;        // 0..15
    const int ty  = threadIdx.y;        // 0..7
    const int tid = ty * 16 + tx;
    const int bw  = blockIdx.x * 64;
    const int bh  = blockIdx.y * 8;
    const int bz  = blockIdx.z;         // b*32 + d
    const int b   = bz >> 5;
    const int d   = bz & 31;

    float acc[27][4];
#pragma unroll
    for (int oc = 0; oc < 27; oc++)
#pragma unroll
        for (int p = 0; p < 4; p++) acc[oc][p] = 0.f;

#pragma unroll 1
    for (int c = 0; c < 32; c++) {
        __syncthreads();
        const float* xc = x + (b * 32 + c) * (D_ * H_ * W_);
        // load x halo tile (1980 elems)
        for (int i = tid; i < 1980; i += 128) {
            int dz = i / 660; int r = i - dz * 660;
            int hy = r / 66;  int wx = r - hy * 66;
            int dg = d + dz - 1, hg = bh + hy - 1, wl = bw + wx - 1;
            float v = 0.f;
            if ((unsigned)dg < (unsigned)D_ && (unsigned)hg < (unsigned)H_ &&
                (unsigned)wl < (unsigned)W_)
                v = xc[(dg * H_ + hg) * W_ + wl];
            xs[(dz * 10 + hy) * 80 + wx] = v;
        }
        // load weights for this input channel: ws[tap*27 + oc]
        for (int i = tid; i < 729; i += 128) {
            int tap = i / 27, oc = i - tap * 27;
            ws[i] = (oc < 26) ? wg[(oc * 32 + c) * 27 + tap]
                              : wc[c * 27 + tap];
        }
        __syncthreads();

#pragma unroll
        for (int kz = 0; kz < 3; kz++)
#pragma unroll
        for (int ky = 0; ky < 3; ky++)
#pragma unroll
        for (int kx = 0; kx < 3; kx++) {
            const float* row = &xs[(kz * 10 + ty + ky) * 80 + tx + kx];
            const float x0 = row[0], x1 = row[16], x2 = row[32], x3 = row[48];
            const float* wp = &ws[((kz * 3 + ky) * 3 + kx) * 27];
#pragma unroll
            for (int oc = 0; oc < 27; oc++) {
                const float wv = wp[oc];           // smem broadcast
                acc[oc][0] += x0 * wv;
                acc[oc][1] += x1 * wv;
                acc[oc][2] += x2 * wv;
                acc[oc][3] += x3 * wv;
            }
        }
    }

    // CSPN normalization + stores
    const int h   = bh + ty;
    const int spb = (bz * H_ + h) * W_ + bw + tx;
#pragma unroll
    for (int p = 0; p < 4; p++) {
        const int sp = spb + p * 16;
        float s = 0.f;
#pragma unroll
        for (int oc = 0; oc < 26; oc++) s += fabsf(acc[oc][p]);
        const float inv = 1.0f / s;
        float sum = 0.f;
#pragma unroll
        for (int oc = 0; oc < 26; oc++) {
            const float wv = acc[oc][p] * inv;
            sum += wv;
            g_w[oc * SP_TOTAL + sp] = wv;
        }
        g_w0[sp] = 1.0f - sum;
        g_b0[sp] = acc[26][p];                     // v = center conv output
    }
}

// ---------------------------------------------------------------------------
// One CSPN diffusion round.
// Block (32,8), tile w_t=32, h_t=8, d_t=1; 1 point/thread; x tile in smem.
// offsets[i] maps to tap i (i<13) or i+1 (i>=13), center tap 13 excluded.
// ---------------------------------------------------------------------------
__global__ __launch_bounds__(256)
void cspn_round_kernel(int r, float* __restrict__ dout)
{
    __shared__ float xs[3 * 10 * 34];

    const int tx  = threadIdx.x;   // 0..31
    const int ty  = threadIdx.y;   // 0..7
    const int tid = ty * 32 + tx;
    const int bw  = blockIdx.x * 32;
    const int bh  = blockIdx.y * 8;
    const int bz  = blockIdx.z;
    const int b   = bz >> 5, d = bz & 31;

    const float* xin  = (r & 1) ? g_b1 : g_b0;
    float*       xout = (r == 7) ? dout : ((r & 1) ? g_b0 : g_b1);

    for (int i = tid; i < 1020; i += 256) {
        int dz = i / 340; int rr = i - dz * 340;
        int hy = rr / 34; int wx = rr - hy * 34;
        int dg = d + dz - 1, hg = bh + hy - 1, wl = bw + wx - 1;
        float v = 0.f;
        if ((unsigned)dg < (unsigned)D_ && (unsigned)hg < (unsigned)H_ &&
            (unsigned)wl < (unsigned)W_)
            v = xin[((b * 32 + dg) * H_ + hg) * W_ + wl];
        xs[(dz * 10 + hy) * 34 + wx] = v;
    }
    __syncthreads();

    const int h  = bh + ty;
    const int sp = (bz * H_ + h) * W_ + bw + tx;

    float acc = g_w0[sp] * xs[(1 * 10 + ty + 1) * 34 + tx + 1];
#pragma unroll
    for (int i = 0; i < 26; i++) {
        const int tap = (i < 13) ? i : i + 1;
        const int kz = tap / 9, ky = (tap / 3) % 3, kx = tap % 3;
        acc += g_w[i * SP_TOTAL + sp] * xs[(kz * 10 + ty + ky) * 34 + tx + kx];
    }
    xout[sp] = acc;
}

// ---------------------------------------------------------------------------
extern "C" void kernel_launch(void* const* d_in, const int* in_sizes, int n_in,
                              void* d_out, int out_size)
{
    const float* x  = (const float*)d_in[0];   // [2,32,32,64,128]
    const float* wg = (const float*)d_in[1];   // [26,32,3,3,3]
    const float* wc = (const float*)d_in[2];   // [1,32,3,3,3]

    (void)in_sizes; (void)n_in; (void)out_size;

    dim3 cb(16, 8), cg(2, 8, 64);              // 1024 blocks
    conv_norm_kernel<<<cg, cb>>>(x, wg, wc);

    dim3 db(32, 8), dg(4, 8, 64);              // 2048 blocks / round
    for (int r = 0; r < 8; r++)
        cspn_round_kernel<<<dg, db>>>(r, (float*)d_out);
}

// round 2
// speedup vs baseline: 1.0038x; 1.0038x over previous
#include <cuda_runtime.h>

#define D_ 32
#define H_ 64
#define W_ 128
#define SP_TOTAL (2 * D_ * H_ * W_)   // 524288 spatial points (B=2)

// Scratch: normalized neighbor weights (26 ch), center weight, ping-pong volumes.
__device__ float g_w [26 * SP_TOTAL];  // [oc][b,d,h,w]  (channel-major for coalescing)
__device__ float g_w0[SP_TOTAL];
__device__ float g_b0[SP_TOTAL];
__device__ float g_b1[SP_TOTAL];

// ---------------------------------------------------------------------------
// Fused conv3d (27 output channels) + CSPN normalization.
// Block: (16,8)=128 threads. Tile: d_t=1, h_t=8, w_t=64; each thread owns
// 4 w-points strided by 16 (keeps LDS conflict-free and STG coalesced).
// ---------------------------------------------------------------------------
__global__ __launch_bounds__(128, 2)
void conv_norm_kernel(const float* __restrict__ x,
                      const float* __restrict__ wg,
                      const float* __restrict__ wc)
{
    __shared__ float xs[3 * 10 * 80];   // halo tile: [dz 3][hy 10][wx 66] stride 80
    __shared__ float ws[729];           // weights for current input channel: [tap][oc]

    const int tx  = threadIdx.x;        // 0..15
    const int ty  = threadIdx.y;        // 0..7
    const int tid = ty * 16 + tx;
    const int bw  = blockIdx.x * 64;
    const int bh  = blockIdx.y * 8;
    const int bz  = blockIdx.z;         // b*32 + d
    const int b   = bz >> 5;
    const int d   = bz & 31;

    float acc[27][4];
#pragma unroll
    for (int oc = 0; oc < 27; oc++)
#pragma unroll
        for (int p = 0; p < 4; p++) acc[oc][p] = 0.f;

#pragma unroll 1
    for (int c = 0; c < 32; c++) {
        __syncthreads();
        const float* xc = x + (b * 32 + c) * (D_ * H_ * W_);
        // load x halo tile (1980 elems)
        for (int i = tid; i < 1980; i += 128) {
            int dz = i / 660; int r = i - dz * 660;
            int hy = r / 66;  int wx = r - hy * 66;
            int dg = d + dz - 1, hg = bh + hy - 1, wl = bw + wx - 1;
            float v = 0.f;
            if ((unsigned)dg < (unsigned)D_ && (unsigned)hg < (unsigned)H_ &&
                (unsigned)wl < (unsigned)W_)
                v = xc[(dg * H_ + hg) * W_ + wl];
            xs[(dz * 10 + hy) * 80 + wx] = v;
        }
        // load weights for this input channel: ws[tap*27 + oc]
        for (int i = tid; i < 729; i += 128) {
            int tap = i / 27, oc = i - tap * 27;
            ws[i] = (oc < 26) ? wg[(oc * 32 + c) * 27 + tap]
                              : wc[c * 27 + tap];
        }
        __syncthreads();

#pragma unroll
        for (int kz = 0; kz < 3; kz++)
#pragma unroll
        for (int ky = 0; ky < 3; ky++)
#pragma unroll
        for (int kx = 0; kx < 3; kx++) {
            const float* row = &xs[(kz * 10 + ty + ky) * 80 + tx + kx];
            const float x0 = row[0], x1 = row[16], x2 = row[32], x3 = row[48];
            const float* wp = &ws[((kz * 3 + ky) * 3 + kx) * 27];
#pragma unroll
            for (int oc = 0; oc < 27; oc++) {
                const float wv = wp[oc];           // smem broadcast
                acc[oc][0] += x0 * wv;
                acc[oc][1] += x1 * wv;
                acc[oc][2] += x2 * wv;
                acc[oc][3] += x3 * wv;
            }
        }
    }

    // CSPN normalization + stores
    const int h   = bh + ty;
    const int spb = (bz * H_ + h) * W_ + bw + tx;
#pragma unroll
    for (int p = 0; p < 4; p++) {
        const int sp = spb + p * 16;
        float s = 0.f;
#pragma unroll
        for (int oc = 0; oc < 26; oc++) s += fabsf(acc[oc][p]);
        const float inv = 1.0f / s;
        float sum = 0.f;
#pragma unroll
        for (int oc = 0; oc < 26; oc++) {
            const float wv = acc[oc][p] * inv;
            sum += wv;
            g_w[oc * SP_TOTAL + sp] = wv;
        }
        g_w0[sp] = 1.0f - sum;
        g_b0[sp] = acc[26][p];                     // v = center conv output
    }
}

// ---------------------------------------------------------------------------
// One CSPN diffusion round.
// Block (32,8), tile w_t=32, h_t=8, d_t=1; 1 point/thread; x tile in smem.
// offsets[i] maps to tap i (i<13) or i+1 (i>=13), center tap 13 excluded.
// ---------------------------------------------------------------------------
__global__ __launch_bounds__(256)
void cspn_round_kernel(int r, float* __restrict__ dout)
{
    __shared__ float xs[3 * 10 * 34];

    const int tx  = threadIdx.x;   // 0..31
    const int ty  = threadIdx.y;   // 0..7
    const int tid = ty * 32 + tx;
    const int bw  = blockIdx.x * 32;
    const int bh  = blockIdx.y * 8;
    const int bz  = blockIdx.z;
    const int b   = bz >> 5, d = bz & 31;

    const float* xin  = (r & 1) ? g_b1 : g_b0;
    float*       xout = (r == 7) ? dout : ((r & 1) ? g_b0 : g_b1);

    for (int i = tid; i < 1020; i += 256) {
        int dz = i / 340; int rr = i - dz * 340;
        int hy = rr / 34; int wx = rr - hy * 34;
        int dg = d + dz - 1, hg = bh + hy - 1, wl = bw + wx - 1;
        float v = 0.f;
        if ((unsigned)dg < (unsigned)D_ && (unsigned)hg < (unsigned)H_ &&
            (unsigned)wl < (unsigned)W_)
            v = xin[((b * 32 + dg) * H_ + hg) * W_ + wl];
        xs[(dz * 10 + hy) * 34 + wx] = v;
    }
    __syncthreads();

    const int h  = bh + ty;
    const int sp = (bz * H_ + h) * W_ + bw + tx;

    float acc = g_w0[sp] * xs[(1 * 10 + ty + 1) * 34 + tx + 1];
#pragma unroll
    for (int i = 0; i < 26; i++) {
        const int tap = (i < 13) ? i : i + 1;
        const int kz = tap / 9, ky = (tap / 3) % 3, kx = tap % 3;
        acc += g_w[i * SP_TOTAL + sp] * xs[(kz * 10 + ty + ky) * 34 + tx + kx];
    }
    xout[sp] = acc;
}

// ---------------------------------------------------------------------------
extern "C" void kernel_launch(void* const* d_in, const int* in_sizes, int n_in,
                              void* d_out, int out_size)
{
    const float* x  = (const float*)d_in[0];   // [2,32,32,64,128]
    const float* wg = (const float*)d_in[1];   // [26,32,3,3,3]
    const float* wc = (const float*)d_in[2];   // [1,32,3,3,3]

    (void)in_sizes; (void)n_in; (void)out_size;

    dim3 cb(16, 8), cg(2, 8, 64);              // 1024 blocks
    conv_norm_kernel<<<cg, cb>>>(x, wg, wc);

    dim3 db(32, 8), dg(4, 8, 64);              // 2048 blocks / round
    for (int r = 0; r < 8; r++)
        cspn_round_kernel<<<dg, db>>>(r, (float*)d_out);
}

// round 3
// speedup vs baseline: 1.0062x; 1.0024x over previous
#include <cuda_runtime.h>

#define D_ 32
#define H_ 64
#define W_ 128
#define SP_TOTAL (2 * D_ * H_ * W_)   // 524288 spatial points (B=2)

// Scratch: normalized neighbor weights (26 ch), center weight, ping-pong volumes.
__device__ float g_w [26 * SP_TOTAL];  // [oc][b,d,h,w]  (channel-major for coalescing)
__device__ float g_w0[SP_TOTAL];
__device__ float g_b0[SP_TOTAL];
__device__ float g_b1[SP_TOTAL];

// ---------------------------------------------------------------------------
// Fused conv3d (27 output channels) + CSPN normalization.
// Block: (16,8)=128 threads. Tile: d_t=1, h_t=8, w_t=64; each thread owns
// 4 w-points strided by 16 (keeps LDS conflict-free and STG coalesced).
// ---------------------------------------------------------------------------
__global__ __launch_bounds__(128, 2)
void conv_norm_kernel(const float* __restrict__ x,
                      const float* __restrict__ wg,
                      const float* __restrict__ wc)
{
    __shared__ float xs[3 * 10 * 80];   // halo tile: [dz 3][hy 10][wx 66] stride 80
    __shared__ float ws[729];           // weights for current input channel: [tap][oc]

    const int tx  = threadIdx.x;        // 0..15
    const int ty  = threadIdx.y;        // 0..7
    const int tid = ty * 16 + tx;
    const int bw  = blockIdx.x * 64;
    const int bh  = blockIdx.y * 8;
    const int bz  = blockIdx.z;         // b*32 + d
    const int b   = bz >> 5;
    const int d   = bz & 31;

    float acc[27][4];
#pragma unroll
    for (int oc = 0; oc < 27; oc++)
#pragma unroll
        for (int p = 0; p < 4; p++) acc[oc][p] = 0.f;

#pragma unroll 1
    for (int c = 0; c < 32; c++) {
        __syncthreads();
        const float* xc = x + (b * 32 + c) * (D_ * H_ * W_);
        // load x halo tile (1980 elems)
        for (int i = tid; i < 1980; i += 128) {
            int dz = i / 660; int r = i - dz * 660;
            int hy = r / 66;  int wx = r - hy * 66;
            int dg = d + dz - 1, hg = bh + hy - 1, wl = bw + wx - 1;
            float v = 0.f;
            if ((unsigned)dg < (unsigned)D_ && (unsigned)hg < (unsigned)H_ &&
                (unsigned)wl < (unsigned)W_)
                v = xc[(dg * H_ + hg) * W_ + wl];
            xs[(dz * 10 + hy) * 80 + wx] = v;
        }
        // load weights for this input channel: ws[tap*27 + oc]
        for (int i = tid; i < 729; i += 128) {
            int tap = i / 27, oc = i - tap * 27;
            ws[i] = (oc < 26) ? wg[(oc * 32 + c) * 27 + tap]
                              : wc[c * 27 + tap];
        }
        __syncthreads();

#pragma unroll
        for (int kz = 0; kz < 3; kz++)
#pragma unroll
        for (int ky = 0; ky < 3; ky++)
#pragma unroll
        for (int kx = 0; kx < 3; kx++) {
            const float* row = &xs[(kz * 10 + ty + ky) * 80 + tx + kx];
            const float x0 = row[0], x1 = row[16], x2 = row[32], x3 = row[48];
            const float* wp = &ws[((kz * 3 + ky) * 3 + kx) * 27];
#pragma unroll
            for (int oc = 0; oc < 27; oc++) {
                const float wv = wp[oc];           // smem broadcast
                acc[oc][0] += x0 * wv;
                acc[oc][1] += x1 * wv;
                acc[oc][2] += x2 * wv;
                acc[oc][3] += x3 * wv;
            }
        }
    }

    // CSPN normalization + stores
    const int h   = bh + ty;
    const int spb = (bz * H_ + h) * W_ + bw + tx;
#pragma unroll
    for (int p = 0; p < 4; p++) {
        const int sp = spb + p * 16;
        float s = 0.f;
#pragma unroll
        for (int oc = 0; oc < 26; oc++) s += fabsf(acc[oc][p]);
        const float inv = 1.0f / s;
        float sum = 0.f;
#pragma unroll
        for (int oc = 0; oc < 26; oc++) {
            const float wv = acc[oc][p] * inv;
            sum += wv;
            g_w[oc * SP_TOTAL + sp] = wv;
        }
        g_w0[sp] = 1.0f - sum;
        g_b0[sp] = acc[26][p];                     // v = center conv output
    }
}

// ---------------------------------------------------------------------------
// One CSPN diffusion round.
// Block (32,8), tile w_t=32, h_t=8, d_t=1; 1 point/thread; x tile in smem.
// offsets[i] maps to tap i (i<13) or i+1 (i>=13), center tap 13 excluded.
// ---------------------------------------------------------------------------
__global__ __launch_bounds__(256)
void cspn_round_kernel(int r, float* __restrict__ dout)
{
    __shared__ float xs[3 * 10 * 34];

    const int tx  = threadIdx.x;   // 0..31
    const int ty  = threadIdx.y;   // 0..7
    const int tid = ty * 32 + tx;
    const int bw  = blockIdx.x * 32;
    const int bh  = blockIdx.y * 8;
    const int bz  = blockIdx.z;
    const int b   = bz >> 5, d = bz & 31;

    const float* xin  = (r & 1) ? g_b1 : g_b0;
    float*       xout = (r == 7) ? dout : ((r & 1) ? g_b0 : g_b1);

    for (int i = tid; i < 1020; i += 256) {
        int dz = i / 340; int rr = i - dz * 340;
        int hy = rr / 34; int wx = rr - hy * 34;
        int dg = d + dz - 1, hg = bh + hy - 1, wl = bw + wx - 1;
        float v = 0.f;
        if ((unsigned)dg < (unsigned)D_ && (unsigned)hg < (unsigned)H_ &&
            (unsigned)wl < (unsigned)W_)
            v = xin[((b * 32 + dg) * H_ + hg) * W_ + wl];
        xs[(dz * 10 + hy) * 34 + wx] = v;
    }
    __syncthreads();

    const int h  = bh + ty;
    const int sp = (bz * H_ + h) * W_ + bw + tx;

    float acc = g_w0[sp] * xs[(1 * 10 + ty + 1) * 34 + tx + 1];
#pragma unroll
    for (int i = 0; i < 26; i++) {
        const int tap = (i < 13) ? i : i + 1;
        const int kz = tap / 9, ky = (tap / 3) % 3, kx = tap % 3;
        acc += g_w[i * SP_TOTAL + sp] * xs[(kz * 10 + ty + ky) * 34 + tx + kx];
    }
    xout[sp] = acc;
}

// ---------------------------------------------------------------------------
extern "C" void kernel_launch(void* const* d_in, const int* in_sizes, int n_in,
                              void* d_out, int out_size)
{
    const float* x  = (const float*)d_in[0];   // [2,32,32,64,128]
    const float* wg = (const float*)d_in[1];   // [26,32,3,3,3]
    const float* wc = (const float*)d_in[2];   // [1,32,3,3,3]

    (void)in_sizes; (void)n_in; (void)out_size;

    dim3 cb(16, 8), cg(2, 8, 64);              // 1024 blocks
    conv_norm_kernel<<<cg, cb>>>(x, wg, wc);

    dim3 db(32, 8), dg(4, 8, 64);              // 2048 blocks / round
    for (int r = 0; r < 8; r++)
        cspn_round_kernel<<<dg, db>>>(r, (float*)d_out);
}